// round 7
// baseline (speedup 1.0000x reference)
#include <cuda_runtime.h>
#include <math.h>

#define NUM_NODES 90000
#define NUM_EDGES 3000000
#define DIM 64
#define LAYERS 100
#define NBLK 352          // ceil(90000/256)
#define NBIN 1024         // degree bins for counting sort

// ---------------- device scratch (static allocation, allowed) ----------------
__device__ short2   g_q0[NUM_NODES * 32];   // int16 state ping (row = 128B)
__device__ short2   g_q1[NUM_NODES * 32];   // int16 state pong
__device__ float    g_acc[NUM_NODES * DIM];
__device__ float    g_dinv[NUM_NODES];
__device__ int      g_deg[NUM_NODES];
__device__ int      g_off[NUM_NODES + 1];
__device__ int      g_fill[NUM_NODES];
__device__ int      g_src[NUM_EDGES];
__device__ int      g_bsum[NBLK];
__device__ int      g_boff[NBLK];
__device__ int      g_hist[NBIN];
__device__ int      g_binoff[NBIN];
__device__ int      g_binfill[NBIN];
__device__ int      g_perm[NUM_NODES];      // nodes sorted by degree
__device__ unsigned g_mx[LAYERS + 2];       // ||y_l||_inf as float bits

// ---------------- preprocessing ----------------
__global__ void k_zero() {
    int i = blockIdx.x * blockDim.x + threadIdx.x;
    if (i < NUM_NODES) g_deg[i] = 0;
    if (i < NBIN) g_hist[i] = 0;
    if (i < LAYERS + 2) g_mx[i] = 0u;
}

__global__ void k_degree(const int* __restrict__ edge_index) {
    int e = blockIdx.x * blockDim.x + threadIdx.x;
    if (e < NUM_EDGES) {
        int c = edge_index[NUM_EDGES + e];  // col = edge_index[1]
        atomicAdd(&g_deg[c], 1);
    }
}

__global__ void k_dinv_fill() {
    int i = blockIdx.x * blockDim.x + threadIdx.x;
    if (i < NUM_NODES) {
        int d = g_deg[i];
        g_dinv[i] = (d > 0) ? rsqrtf((float)d) : 0.0f;
        g_fill[i] = 0;
        atomicAdd(&g_hist[min(d, NBIN - 1)], 1);
    }
}

// 3-phase coalesced exclusive scan of g_deg -> g_off
__global__ void k_blocksum() {
    __shared__ int sh[256];
    int t = threadIdx.x;
    int i = blockIdx.x * 256 + t;
    sh[t] = (i < NUM_NODES) ? g_deg[i] : 0;
    __syncthreads();
    for (int o = 128; o > 0; o >>= 1) {
        if (t < o) sh[t] += sh[t + o];
        __syncthreads();
    }
    if (t == 0) g_bsum[blockIdx.x] = sh[0];
}

__global__ void k_scan_bsum() {
    __shared__ int sh[512];
    int t = threadIdx.x;
    int v = (t < NBLK) ? g_bsum[t] : 0;
    sh[t] = v;
    __syncthreads();
    for (int o = 1; o < 512; o <<= 1) {
        int tmp = (t >= o) ? sh[t - o] : 0;
        __syncthreads();
        sh[t] += tmp;
        __syncthreads();
    }
    if (t < NBLK) g_boff[t] = sh[t] - v;  // exclusive
}

__global__ void k_expand() {
    __shared__ int sh[256];
    int t = threadIdx.x;
    int i = blockIdx.x * 256 + t;
    int v = (i < NUM_NODES) ? g_deg[i] : 0;
    sh[t] = v;
    __syncthreads();
    for (int o = 1; o < 256; o <<= 1) {
        int tmp = (t >= o) ? sh[t - o] : 0;
        __syncthreads();
        sh[t] += tmp;
        __syncthreads();
    }
    if (i < NUM_NODES) g_off[i] = g_boff[blockIdx.x] + sh[t] - v;
    if (i == 0) g_off[NUM_NODES] = NUM_EDGES;
}

// exclusive scan of the 1024 degree bins; zero fill counters
__global__ void k_scan_bins() {
    __shared__ int sh[NBIN];
    int t = threadIdx.x;
    int v = g_hist[t];
    sh[t] = v;
    __syncthreads();
    for (int o = 1; o < NBIN; o <<= 1) {
        int tmp = (t >= o) ? sh[t - o] : 0;
        __syncthreads();
        sh[t] += tmp;
        __syncthreads();
    }
    g_binoff[t] = sh[t] - v;
    g_binfill[t] = 0;
}

__global__ void k_scatter_perm() {
    int i = blockIdx.x * blockDim.x + threadIdx.x;
    if (i < NUM_NODES) {
        int b = min(g_deg[i], NBIN - 1);
        int p = g_binoff[b] + atomicAdd(&g_binfill[b], 1);
        g_perm[p] = i;
    }
}

__global__ void k_build_csr(const int* __restrict__ edge_index) {
    int e = blockIdx.x * blockDim.x + threadIdx.x;
    if (e < NUM_EDGES) {
        int r = edge_index[e];              // row
        int c = edge_index[NUM_EDGES + e];  // col
        int p = g_off[c] + atomicAdd(&g_fill[c], 1);
        g_src[p] = r;
    }
}

// pass A: g_mx[0] = max |dinv*emb|
__global__ void k_init_max(const float* __restrict__ emb) {
    __shared__ float sm[256];
    int t = threadIdx.x;
    int i = blockIdx.x * 256 + t;  // over N*32 float2 slots
    float m = 0.0f;
    if (i < NUM_NODES * 32) {
        float d = g_dinv[i >> 5];
        float2 v = ((const float2*)emb)[i];
        m = fmaxf(fabsf(d * v.x), fabsf(d * v.y));
    }
    sm[t] = m;
    __syncthreads();
    for (int o = 128; o > 0; o >>= 1) {
        if (t < o) sm[t] = fmaxf(sm[t], sm[t + o]);
        __syncthreads();
    }
    if (t == 0) atomicMax(&g_mx[0], __float_as_uint(sm[0]));
}

// pass B: acc = emb; q0 = quantize(dinv*emb, scale=g_mx[0])
__global__ void k_init_quant(const float* __restrict__ emb) {
    int i = blockIdx.x * blockDim.x + threadIdx.x;
    if (i < NUM_NODES * 32) {
        float d = g_dinv[i >> 5];
        float S = __uint_as_float(g_mx[0]);
        float enc = (S > 0.0f) ? 32767.0f / S : 0.0f;
        float2 v = ((const float2*)emb)[i];
        ((float2*)g_acc)[i] = v;
        int qx = __float2int_rn(d * v.x * enc);
        int qy = __float2int_rn(d * v.y * enc);
        qx = max(-32767, min(32767, qx));
        qy = max(-32767, min(32767, qy));
        g_q0[i] = make_short2((short)qx, (short)qy);
    }
}

// ---------------- one layer: warp per (degree-sorted) destination node ----------
// Half-warp edge pairing: lanes 0-15 process even edges, lanes 16-31 odd edges;
// each lane loads int2 (dims 4c..4c+3) so one gather LDG covers 2 edges.
__global__ void __launch_bounds__(256) k_conv(int l, int flip) {
    const int2* __restrict__ qin  = (const int2*)(flip ? g_q1 : g_q0);
    int2*       __restrict__ qout = (int2*)(flip ? g_q0 : g_q1);

    int w    = (blockIdx.x * blockDim.x + threadIdx.x) >> 5;
    int lane = threadIdx.x & 31;
    int wid  = threadIdx.x >> 5;
    int half = lane >> 4;   // 0 or 1
    int col  = lane & 15;   // int2 column within 128B row
    bool active = (w < NUM_NODES);

    int node = active ? g_perm[w] : 0;

    float S_dec = __uint_as_float(g_mx[(l == 0) ? 0 : (l - 1)]);
    float S_enc = __uint_as_float(g_mx[l]);
    float dec  = S_dec * (1.0f / 32767.0f);
    float encr = (S_enc > 0.0f) ? (32767.0f / S_enc) : 0.0f;

    int beg = 0, end = 0;
    if (active) { beg = g_off[node]; end = g_off[node + 1]; }

    int a0 = 0, a1 = 0, a2 = 0, a3 = 0;

    int j = beg;
#pragma unroll 4
    for (; j + 2 <= end; j += 2) {
        int s0 = __ldg(&g_src[j]);       // broadcast (sequential, L1 hit)
        int s1 = __ldg(&g_src[j + 1]);
        int s  = half ? s1 : s0;
        int2 v = __ldg(&qin[s * 16 + col]);
        a0 += (v.x << 16) >> 16;
        a1 += v.x >> 16;
        a2 += (v.y << 16) >> 16;
        a3 += v.y >> 16;
    }
    if (j < end) {  // odd remainder: only half 0 contributes
        int s0 = __ldg(&g_src[j]);
        int2 v = __ldg(&qin[s0 * 16 + col]);
        if (!half) {
            a0 += (v.x << 16) >> 16;
            a1 += v.x >> 16;
            a2 += (v.y << 16) >> 16;
            a3 += v.y >> 16;
        }
    }

    // combine the two half-warp partial sums (exact integer)
    a0 += __shfl_xor_sync(0xffffffffu, a0, 16);
    a1 += __shfl_xor_sync(0xffffffffu, a1, 16);
    a2 += __shfl_xor_sync(0xffffffffu, a2, 16);
    a3 += __shfl_xor_sync(0xffffffffu, a3, 16);

    float m = 0.0f;
    if (active && half == 0) {
        float dc = g_dinv[node];
        float xn0 = dc * ((float)a0 * dec);
        float xn1 = dc * ((float)a1 * dec);
        float xn2 = dc * ((float)a2 * dec);
        float xn3 = dc * ((float)a3 * dec);

        size_t o = (size_t)node * 16 + col;
        float4* acc4 = (float4*)g_acc;
        float4 ac = acc4[o];
        ac.x += xn0; ac.y += xn1; ac.z += xn2; ac.w += xn3;
        acc4[o] = ac;

        float t0 = dc * xn0, t1 = dc * xn1, t2 = dc * xn2, t3 = dc * xn3;
        int q0i = max(-32767, min(32767, __float2int_rn(t0 * encr)));
        int q1i = max(-32767, min(32767, __float2int_rn(t1 * encr)));
        int q2i = max(-32767, min(32767, __float2int_rn(t2 * encr)));
        int q3i = max(-32767, min(32767, __float2int_rn(t3 * encr)));
        int lo = (q0i & 0xFFFF) | (q1i << 16);
        int hi = (q2i & 0xFFFF) | (q3i << 16);
        qout[o] = make_int2(lo, hi);

        m = fmaxf(fmaxf(fabsf(t0), fabsf(t1)), fmaxf(fabsf(t2), fabsf(t3)));
    }

    // block max of |t| -> g_mx[l+1]  (exact ||y_{l+1}||inf)
#pragma unroll
    for (int o = 16; o > 0; o >>= 1)
        m = fmaxf(m, __shfl_xor_sync(0xffffffffu, m, o));
    __shared__ float smax[8];
    if (lane == 0) smax[wid] = m;
    __syncthreads();
    if (threadIdx.x == 0) {
        float bm = smax[0];
#pragma unroll
        for (int k = 1; k < 8; k++) bm = fmaxf(bm, smax[k]);
        atomicMax(&g_mx[l + 1], __float_as_uint(bm));
    }
}

__global__ void k_final(float* __restrict__ out) {
    int i = blockIdx.x * blockDim.x + threadIdx.x;
    if (i < NUM_NODES * DIM) {
        out[i] = g_acc[i] * (1.0f / (float)(LAYERS + 1));
    }
}

// ---------------- launch ----------------
extern "C" void kernel_launch(void* const* d_in, const int* in_sizes, int n_in,
                              void* d_out, int out_size) {
    const float* emb = (const float*)d_in[0];
    const int*   ei  = (const int*)d_in[1];
    float*       out = (float*)d_out;

    const int TB = 256;
    const int nb_nodes = (NUM_NODES + TB - 1) / TB;
    const int nb_edges = (NUM_EDGES + TB - 1) / TB;
    const int nb_feat  = (NUM_NODES * DIM + TB - 1) / TB;
    const int nb_half  = (NUM_NODES * 32 + TB - 1) / TB;
    const int nb_conv  = (NUM_NODES * 32 + TB - 1) / TB;

    k_zero<<<nb_nodes, TB>>>();
    k_degree<<<nb_edges, TB>>>(ei);
    k_dinv_fill<<<nb_nodes, TB>>>();
    k_blocksum<<<NBLK, 256>>>();
    k_scan_bsum<<<1, 512>>>();
    k_expand<<<NBLK, 256>>>();
    k_scan_bins<<<1, NBIN>>>();
    k_scatter_perm<<<nb_nodes, TB>>>();
    k_build_csr<<<nb_edges, TB>>>(ei);
    k_init_max<<<nb_half, TB>>>(emb);
    k_init_quant<<<nb_half, TB>>>(emb);

    for (int l = 0; l < LAYERS; l++) {
        k_conv<<<nb_conv, TB>>>(l, l & 1);
    }

    k_final<<<nb_feat, TB>>>(out);
}

// round 9
// speedup vs baseline: 1.0544x; 1.0544x over previous
#include <cuda_runtime.h>
#include <math.h>

#define NUM_NODES 90000
#define NUM_EDGES 3000000
#define DIM 64
#define LAYERS 100
#define NBLK 352          // ceil(90000/256)

// ---------------- device scratch (static allocation, allowed) ----------------
__device__ int4     g_q0[NUM_NODES * 8];    // int16 state ping (row = 128B = 8 int4)
__device__ int4     g_q1[NUM_NODES * 8];    // int16 state pong
__device__ float    g_acc[NUM_NODES * DIM];
__device__ float    g_dinv[NUM_NODES];
__device__ int      g_deg[NUM_NODES];
__device__ int      g_off[NUM_NODES + 1];
__device__ int      g_fill[NUM_NODES];
__device__ int      g_src[NUM_EDGES];
__device__ int      g_bsum[NBLK];
__device__ int      g_boff[NBLK];
__device__ unsigned g_mx[LAYERS + 2];       // ||y_l||_inf as float bits

// ---------------- preprocessing ----------------
__global__ void k_zero() {
    int i = blockIdx.x * blockDim.x + threadIdx.x;
    if (i < NUM_NODES) g_deg[i] = 0;
    if (i < LAYERS + 2) g_mx[i] = 0u;
}

__global__ void k_degree(const int* __restrict__ edge_index) {
    int e = blockIdx.x * blockDim.x + threadIdx.x;
    if (e < NUM_EDGES) {
        int c = edge_index[NUM_EDGES + e];  // col = edge_index[1]
        atomicAdd(&g_deg[c], 1);
    }
}

__global__ void k_dinv_fill() {
    int i = blockIdx.x * blockDim.x + threadIdx.x;
    if (i < NUM_NODES) {
        int d = g_deg[i];
        g_dinv[i] = (d > 0) ? rsqrtf((float)d) : 0.0f;
        g_fill[i] = 0;
    }
}

// 3-phase coalesced exclusive scan of g_deg -> g_off
__global__ void k_blocksum() {
    __shared__ int sh[256];
    int t = threadIdx.x;
    int i = blockIdx.x * 256 + t;
    sh[t] = (i < NUM_NODES) ? g_deg[i] : 0;
    __syncthreads();
    for (int o = 128; o > 0; o >>= 1) {
        if (t < o) sh[t] += sh[t + o];
        __syncthreads();
    }
    if (t == 0) g_bsum[blockIdx.x] = sh[0];
}

__global__ void k_scan_bsum() {
    __shared__ int sh[512];
    int t = threadIdx.x;
    int v = (t < NBLK) ? g_bsum[t] : 0;
    sh[t] = v;
    __syncthreads();
    for (int o = 1; o < 512; o <<= 1) {
        int tmp = (t >= o) ? sh[t - o] : 0;
        __syncthreads();
        sh[t] += tmp;
        __syncthreads();
    }
    if (t < NBLK) g_boff[t] = sh[t] - v;  // exclusive
}

__global__ void k_expand() {
    __shared__ int sh[256];
    int t = threadIdx.x;
    int i = blockIdx.x * 256 + t;
    int v = (i < NUM_NODES) ? g_deg[i] : 0;
    sh[t] = v;
    __syncthreads();
    for (int o = 1; o < 256; o <<= 1) {
        int tmp = (t >= o) ? sh[t - o] : 0;
        __syncthreads();
        sh[t] += tmp;
        __syncthreads();
    }
    if (i < NUM_NODES) g_off[i] = g_boff[blockIdx.x] + sh[t] - v;
    if (i == 0) g_off[NUM_NODES] = NUM_EDGES;
}

__global__ void k_build_csr(const int* __restrict__ edge_index) {
    int e = blockIdx.x * blockDim.x + threadIdx.x;
    if (e < NUM_EDGES) {
        int r = edge_index[e];              // row
        int c = edge_index[NUM_EDGES + e];  // col
        int p = g_off[c] + atomicAdd(&g_fill[c], 1);
        g_src[p] = r;
    }
}

// pass A: g_mx[0] = max |dinv*emb|
__global__ void k_init_max(const float* __restrict__ emb) {
    __shared__ float sm[256];
    int t = threadIdx.x;
    int i = blockIdx.x * 256 + t;  // over N*32 float2 slots
    float m = 0.0f;
    if (i < NUM_NODES * 32) {
        float d = g_dinv[i >> 5];
        float2 v = ((const float2*)emb)[i];
        m = fmaxf(fabsf(d * v.x), fabsf(d * v.y));
    }
    sm[t] = m;
    __syncthreads();
    for (int o = 128; o > 0; o >>= 1) {
        if (t < o) sm[t] = fmaxf(sm[t], sm[t + o]);
        __syncthreads();
    }
    if (t == 0) atomicMax(&g_mx[0], __float_as_uint(sm[0]));
}

// pass B: acc = emb; q0 = quantize(dinv*emb, scale=g_mx[0])
__global__ void k_init_quant(const float* __restrict__ emb) {
    int i = blockIdx.x * blockDim.x + threadIdx.x;
    if (i < NUM_NODES * 32) {
        float d = g_dinv[i >> 5];
        float S = __uint_as_float(g_mx[0]);
        float enc = (S > 0.0f) ? 32767.0f / S : 0.0f;
        float2 v = ((const float2*)emb)[i];
        ((float2*)g_acc)[i] = v;
        int qx = __float2int_rn(d * v.x * enc);
        int qy = __float2int_rn(d * v.y * enc);
        qx = max(-32767, min(32767, qx));
        qy = max(-32767, min(32767, qy));
        ((short2*)g_q0)[i] = make_short2((short)qx, (short)qy);
    }
}

// ---------------- one layer: warp per destination node --------------------------
// Quarter-warp gather: q = lane>>3 picks the edge within a group of 4,
// c = lane&7 picks the int4 column. One LDG.128 serves 4 edges (4 rows x 128B).
__global__ void __launch_bounds__(256) k_conv(int l, int flip) {
    const int4* __restrict__ qin  = flip ? g_q1 : g_q0;
    int4*       __restrict__ qout = flip ? g_q0 : g_q1;

    int node = (blockIdx.x * blockDim.x + threadIdx.x) >> 5;  // dest node
    int lane = threadIdx.x & 31;
    int wid  = threadIdx.x >> 5;
    int q    = lane >> 3;   // 0..3 : edge slot
    int c    = lane & 7;    // int4 column within 128B row
    bool active = (node < NUM_NODES);

    float S_dec = __uint_as_float(g_mx[(l == 0) ? 0 : (l - 1)]);
    float S_enc = __uint_as_float(g_mx[l]);
    float dec  = S_dec * (1.0f / 32767.0f);
    float encr = (S_enc > 0.0f) ? (32767.0f / S_enc) : 0.0f;

    int beg = 0, end = 0;
    if (active) { beg = g_off[node]; end = g_off[node + 1]; }

    int a0 = 0, a1 = 0, a2 = 0, a3 = 0, a4 = 0, a5 = 0, a6 = 0, a7 = 0;

    int j = beg;
#pragma unroll 2
    for (; j + 4 <= end; j += 4) {
        int s0 = __ldg(&g_src[j]);      // broadcast, sequential stream
        int s1 = __ldg(&g_src[j + 1]);
        int s2 = __ldg(&g_src[j + 2]);
        int s3 = __ldg(&g_src[j + 3]);
        int s  = (q == 0) ? s0 : (q == 1) ? s1 : (q == 2) ? s2 : s3;
        int4 v = __ldg(&qin[s * 8 + c]);
        a0 += (v.x << 16) >> 16;  a1 += v.x >> 16;
        a2 += (v.y << 16) >> 16;  a3 += v.y >> 16;
        a4 += (v.z << 16) >> 16;  a5 += v.z >> 16;
        a6 += (v.w << 16) >> 16;  a7 += v.w >> 16;
    }
    int rem = end - j;
    if (rem > 0) {
        int sq = __ldg(&g_src[j + ((q < rem) ? q : 0)]);
        int4 v = __ldg(&qin[sq * 8 + c]);
        if (q < rem) {
            a0 += (v.x << 16) >> 16;  a1 += v.x >> 16;
            a2 += (v.y << 16) >> 16;  a3 += v.y >> 16;
            a4 += (v.z << 16) >> 16;  a5 += v.z >> 16;
            a6 += (v.w << 16) >> 16;  a7 += v.w >> 16;
        }
    }

    // combine across the 4 quarters (exact integer); result lands in q==0 lanes
    a0 += __shfl_xor_sync(0xffffffffu, a0, 8);  a0 += __shfl_xor_sync(0xffffffffu, a0, 16);
    a1 += __shfl_xor_sync(0xffffffffu, a1, 8);  a1 += __shfl_xor_sync(0xffffffffu, a1, 16);
    a2 += __shfl_xor_sync(0xffffffffu, a2, 8);  a2 += __shfl_xor_sync(0xffffffffu, a2, 16);
    a3 += __shfl_xor_sync(0xffffffffu, a3, 8);  a3 += __shfl_xor_sync(0xffffffffu, a3, 16);
    a4 += __shfl_xor_sync(0xffffffffu, a4, 8);  a4 += __shfl_xor_sync(0xffffffffu, a4, 16);
    a5 += __shfl_xor_sync(0xffffffffu, a5, 8);  a5 += __shfl_xor_sync(0xffffffffu, a5, 16);
    a6 += __shfl_xor_sync(0xffffffffu, a6, 8);  a6 += __shfl_xor_sync(0xffffffffu, a6, 16);
    a7 += __shfl_xor_sync(0xffffffffu, a7, 8);  a7 += __shfl_xor_sync(0xffffffffu, a7, 16);

    float m = 0.0f;
    if (active && q == 0) {
        float dc = g_dinv[node];
        float xn0 = dc * ((float)a0 * dec);
        float xn1 = dc * ((float)a1 * dec);
        float xn2 = dc * ((float)a2 * dec);
        float xn3 = dc * ((float)a3 * dec);
        float xn4 = dc * ((float)a4 * dec);
        float xn5 = dc * ((float)a5 * dec);
        float xn6 = dc * ((float)a6 * dec);
        float xn7 = dc * ((float)a7 * dec);

        float4* acc4 = (float4*)g_acc;
        size_t o = (size_t)node * 16 + 2 * c;
        float4 acA = acc4[o];
        float4 acB = acc4[o + 1];
        acA.x += xn0; acA.y += xn1; acA.z += xn2; acA.w += xn3;
        acB.x += xn4; acB.y += xn5; acB.z += xn6; acB.w += xn7;
        acc4[o]     = acA;
        acc4[o + 1] = acB;

        float t0 = dc * xn0, t1 = dc * xn1, t2 = dc * xn2, t3 = dc * xn3;
        float t4 = dc * xn4, t5 = dc * xn5, t6 = dc * xn6, t7 = dc * xn7;
        int q0i = max(-32767, min(32767, __float2int_rn(t0 * encr)));
        int q1i = max(-32767, min(32767, __float2int_rn(t1 * encr)));
        int q2i = max(-32767, min(32767, __float2int_rn(t2 * encr)));
        int q3i = max(-32767, min(32767, __float2int_rn(t3 * encr)));
        int q4i = max(-32767, min(32767, __float2int_rn(t4 * encr)));
        int q5i = max(-32767, min(32767, __float2int_rn(t5 * encr)));
        int q6i = max(-32767, min(32767, __float2int_rn(t6 * encr)));
        int q7i = max(-32767, min(32767, __float2int_rn(t7 * encr)));
        int4 w;
        w.x = (q0i & 0xFFFF) | (q1i << 16);
        w.y = (q2i & 0xFFFF) | (q3i << 16);
        w.z = (q4i & 0xFFFF) | (q5i << 16);
        w.w = (q6i & 0xFFFF) | (q7i << 16);
        qout[(size_t)node * 8 + c] = w;

        m = fmaxf(fmaxf(fmaxf(fabsf(t0), fabsf(t1)), fmaxf(fabsf(t2), fabsf(t3))),
                  fmaxf(fmaxf(fabsf(t4), fabsf(t5)), fmaxf(fabsf(t6), fabsf(t7))));
    }

    // block max of |t| -> g_mx[l+1]  (exact ||y_{l+1}||inf)
#pragma unroll
    for (int o = 16; o > 0; o >>= 1)
        m = fmaxf(m, __shfl_xor_sync(0xffffffffu, m, o));
    __shared__ float smax[8];
    if (lane == 0) smax[wid] = m;
    __syncthreads();
    if (threadIdx.x == 0) {
        float bm = smax[0];
#pragma unroll
        for (int k = 1; k < 8; k++) bm = fmaxf(bm, smax[k]);
        atomicMax(&g_mx[l + 1], __float_as_uint(bm));
    }
}

__global__ void k_final(float* __restrict__ out) {
    int i = blockIdx.x * blockDim.x + threadIdx.x;
    if (i < NUM_NODES * DIM) {
        out[i] = g_acc[i] * (1.0f / (float)(LAYERS + 1));
    }
}

// ---------------- launch ----------------
extern "C" void kernel_launch(void* const* d_in, const int* in_sizes, int n_in,
                              void* d_out, int out_size) {
    const float* emb = (const float*)d_in[0];
    const int*   ei  = (const int*)d_in[1];
    float*       out = (float*)d_out;

    const int TB = 256;
    const int nb_nodes = (NUM_NODES + TB - 1) / TB;
    const int nb_edges = (NUM_EDGES + TB - 1) / TB;
    const int nb_feat  = (NUM_NODES * DIM + TB - 1) / TB;
    const int nb_half  = (NUM_NODES * 32 + TB - 1) / TB;
    const int nb_conv  = (NUM_NODES * 32 + TB - 1) / TB;

    k_zero<<<nb_nodes, TB>>>();
    k_degree<<<nb_edges, TB>>>(ei);
    k_dinv_fill<<<nb_nodes, TB>>>();
    k_blocksum<<<NBLK, 256>>>();
    k_scan_bsum<<<1, 512>>>();
    k_expand<<<NBLK, 256>>>();
    k_build_csr<<<nb_edges, TB>>>(ei);
    k_init_max<<<nb_half, TB>>>(emb);
    k_init_quant<<<nb_half, TB>>>(emb);

    for (int l = 0; l < LAYERS; l++) {
        k_conv<<<nb_conv, TB>>>(l, l & 1);
    }

    k_final<<<nb_feat, TB>>>(out);
}